// round 16
// baseline (speedup 1.0000x reference)
#include <cuda_runtime.h>
#include <cuda_bf16.h>
#include <math.h>
#include <stdint.h>

// Problem dims
#define BB 256
#define TT 512
#define CHD 1024
#define LHD 1024
#define SSS 16
#define NNN 16
#define SB 4096
#define KW 1536

// ---------------- scratch (device globals) ----------------------------------
__device__ float g_c[BB * CHD];
__device__ float g_gc[BB * 4 * CHD];
__device__ float g_decin[SB * 2 * LHD];
__device__ float g_prectx[SB * 4 * LHD];      // permuted cols
__device__ float g_dc[SB * LHD];
__device__ float g_pbdec[4 * LHD];            // permuted dec bias (bih+bhh)
__device__ __nv_bfloat16 g_hhi[SB * LHD], g_hlo[SB * LHD];       // ping
__device__ __nv_bfloat16 g_h2hi[SB * LHD], g_h2lo[SB * LHD];     // pong
__device__ __nv_bfloat16 g_whi[4 * LHD * KW],  g_wlo[4 * LHD * KW];   // permuted rows
__device__ __nv_bfloat16 g_xhi[BB * SSS * NNN * TT], g_xlo[BB * SSS * NNN * TT];
__device__ __nv_bfloat16 g_cwhi[4 * CHD * CHD], g_cwlo[4 * CHD * CHD];
__device__ __nv_bfloat16 g_wctxhi[4 * LHD * 2 * LHD], g_wctxlo[4 * LHD * 2 * LHD]; // permuted rows
__device__ __nv_bfloat16 g_owhi[TT * LHD], g_owlo[TT * LHD];
__device__ __nv_bfloat16 g_pwhi[2 * LHD * CHD], g_pwlo[2 * LHD * CHD];
__device__ __nv_bfloat16 g_cohi[SSS * BB * CHD], g_colo[SSS * BB * CHD];
__device__ __nv_bfloat16 g_dinhi[SB * 2 * LHD], g_dinlo[SB * 2 * LHD];
__device__ __nv_bfloat16 g_histhi[NNN * SB * LHD], g_histlo[NNN * SB * LHD];

__device__ __forceinline__ float sigm(float x) { return 1.0f / (1.0f + expf(-x)); }
__device__ __forceinline__ void split_bf(float v, __nv_bfloat16& hi, __nv_bfloat16& lo) {
    hi = __float2bfloat16(v);
    lo = __float2bfloat16(v - __bfloat162float(hi));
}
// gate-block permutation: new row r -> orig row
__host__ __device__ __forceinline__ int perm_orig(int r) {
    int cb = r >> 7, gate = (r >> 5) & 3, u5 = r & 31;
    return gate * 1024 + cb * 32 + u5;
}

// ==================== PTX helpers (sm_80-portable only) =====================
__device__ __forceinline__ uint32_t smem_u32(const void* p) {
    uint32_t a;
    asm("{ .reg .u64 t; cvta.to.shared.u64 t, %1; cvt.u32.u64 %0, t; }" : "=r"(a) : "l"(p));
    return a;
}
__device__ __forceinline__ void cp16(uint32_t d, const void* s) {
    asm volatile("cp.async.cg.shared.global [%0], [%1], 16;" :: "r"(d), "l"(s));
}
__device__ __forceinline__ void cp_commit() {
    asm volatile("cp.async.commit_group;" ::: "memory");
}
__device__ __forceinline__ void cp_wait1() {
    asm volatile("cp.async.wait_group 1;" ::: "memory");
}
__device__ __forceinline__ void ldsm4(uint32_t* r, uint32_t addr) {
    asm volatile("ldmatrix.sync.aligned.m8n8.x4.shared.b16 {%0,%1,%2,%3}, [%4];"
                 : "=r"(r[0]), "=r"(r[1]), "=r"(r[2]), "=r"(r[3]) : "r"(addr));
}
__device__ __forceinline__ void mma16816(float* c, const uint32_t* a, uint32_t b0, uint32_t b1) {
    asm volatile(
        "mma.sync.aligned.m16n8k16.row.col.f32.bf16.bf16.f32 "
        "{%0,%1,%2,%3}, {%4,%5,%6,%7}, {%8,%9}, {%0,%1,%2,%3};"
        : "+f"(c[0]), "+f"(c[1]), "+f"(c[2]), "+f"(c[3])
        : "r"(a[0]), "r"(a[1]), "r"(a[2]), "r"(a[3]), "r"(b0), "r"(b1));
}

// merged-pass 2-stage: Ahi|Alo|Bhi|Blo @ 80B stride, BK=32
#define G2STAGE 40960
#define G2SMEM (2 * G2STAGE)   // 81920 -> 2 CTAs/SM (epilogue tile 67584 fits)

// ===== gates GEMM (dec loop): R14 mainloop + fused LSTM-cell epilogue =======
__global__ void __launch_bounds__(256, 2) gemm_gates_kernel(
    int n,
    const __nv_bfloat16* __restrict__ hsrc_hi, const __nv_bfloat16* __restrict__ hsrc_lo,
    __nv_bfloat16* __restrict__ hdst_hi, __nv_bfloat16* __restrict__ hdst_lo)
{
    extern __shared__ char smem[];
    const uint32_t sb = smem_u32(smem);
    const int tid  = threadIdx.x;
    const int lane = tid & 31;
    const int wid  = tid >> 5;
    const int mbase = blockIdx.y * 128;
    const int nbase = blockIdx.x * 128;
    const int wm = (wid & 3) * 32;
    const int wn = (wid >> 2) * 64;

    const int K    = (n == 0) ? 1024 : KW;
    const int NK   = K / 32;
    const int wofs = (n == 0) ? 512 : 0;

    const int lrow = tid >> 2;
    const int lc   = tid & 3;
    const int t8 = lane >> 3;
    const int r8 = lane & 7;
    const uint32_t a_lane = (uint32_t)((wm + (t8 & 1) * 8 + r8) * 80 + (t8 >> 1) * 16);
    const uint32_t b_lane = (uint32_t)((wn + (t8 >> 1) * 8 + r8) * 80 + (t8 & 1) * 16);

    float acc[2][8][4];
#pragma unroll
    for (int i = 0; i < 2; i++)
#pragma unroll
        for (int j = 0; j < 8; j++)
#pragma unroll
            for (int v = 0; v < 4; v++) acc[i][j][v] = 0.0f;

    auto load_chunk = [&](int kt) {
        const int slot = kt & 1;
        const int kk = kt * 32;
        const uint32_t st = sb + slot * G2STAGE;
        int row = lrow;
#pragma unroll
        for (int it = 0; it < 2; it++, row += 64) {
            const uint32_t d = st + row * 80 + lc * 16;
            if (n > 0 && kk < 512) {
                const int b = (mbase + row) & 255, s = (mbase + row) >> 8;
                const size_t ao = ((size_t)(b * (SSS * NNN) + s * NNN + n - 1)) * TT + kk + lc * 8;
                cp16(d,         g_xhi + ao);
                cp16(d + 10240, g_xlo + ao);
            } else {
                const int hc = (n == 0) ? kk : (kk - 512);
                const size_t ao = (size_t)(mbase + row) * LHD + hc + lc * 8;
                cp16(d,         hsrc_hi + ao);
                cp16(d + 10240, hsrc_lo + ao);
            }
            const size_t bo = (size_t)(nbase + row) * KW + wofs + kk + lc * 8;
            cp16(d + 20480, g_whi + bo);
            cp16(d + 30720, g_wlo + bo);
        }
    };

    load_chunk(0); cp_commit();
    load_chunk(1); cp_commit();

    for (int kt = 0; kt < NK; kt++) {
        cp_wait1();
        __syncthreads();
        const uint32_t st = sb + (kt & 1) * G2STAGE;
#pragma unroll
        for (int ks = 0; ks < 2; ks++) {
            uint32_t ah[2][4], bh[4][4];
#pragma unroll
            for (int mi = 0; mi < 2; mi++)
                ldsm4(ah[mi], st + a_lane + mi * 16 * 80 + ks * 32);
#pragma unroll
            for (int bi = 0; bi < 4; bi++)
                ldsm4(bh[bi], st + 20480 + b_lane + bi * 16 * 80 + ks * 32);
#pragma unroll
            for (int mi = 0; mi < 2; mi++)
#pragma unroll
                for (int ni = 0; ni < 8; ni++)
                    mma16816(acc[mi][ni], ah[mi], bh[ni >> 1][(ni & 1) * 2], bh[ni >> 1][(ni & 1) * 2 + 1]);
            {
                uint32_t al[2][4];
#pragma unroll
                for (int mi = 0; mi < 2; mi++)
                    ldsm4(al[mi], st + 10240 + a_lane + mi * 16 * 80 + ks * 32);
#pragma unroll
                for (int mi = 0; mi < 2; mi++)
#pragma unroll
                    for (int ni = 0; ni < 8; ni++)
                        mma16816(acc[mi][ni], al[mi], bh[ni >> 1][(ni & 1) * 2], bh[ni >> 1][(ni & 1) * 2 + 1]);
            }
            {
                uint32_t bl[4][4];
#pragma unroll
                for (int bi = 0; bi < 4; bi++)
                    ldsm4(bl[bi], st + 30720 + b_lane + bi * 16 * 80 + ks * 32);
#pragma unroll
                for (int mi = 0; mi < 2; mi++)
#pragma unroll
                    for (int ni = 0; ni < 8; ni++)
                        mma16816(acc[mi][ni], ah[mi], bl[ni >> 1][(ni & 1) * 2], bl[ni >> 1][(ni & 1) * 2 + 1]);
            }
        }
        __syncthreads();
        if (kt + 2 < NK) load_chunk(kt + 2);
        cp_commit();
    }

    // ---- fused LSTM cell epilogue (gate-block permuted cols) ----
    __syncthreads();                       // done with pipeline smem
    float* sm = (float*)smem;              // 128 x 132 fp32 tile
#pragma unroll
    for (int mi = 0; mi < 2; mi++) {
        const int r0 = wm + mi * 16 + (lane >> 2);
        const int c0 = wn + (lane & 3) * 2;
#pragma unroll
        for (int ni = 0; ni < 8; ni++) {
            sm[r0 * 132 + c0 + ni * 8]           = acc[mi][ni][0];
            sm[r0 * 132 + c0 + ni * 8 + 1]       = acc[mi][ni][1];
            sm[(r0 + 8) * 132 + c0 + ni * 8]     = acc[mi][ni][2];
            sm[(r0 + 8) * 132 + c0 + ni * 8 + 1] = acc[mi][ni][3];
        }
    }
    __syncthreads();

    const int row = tid >> 1;
    const int ub  = (tid & 1) * 16;
    const int gr  = mbase + row;
    const int unit0 = (nbase >> 2) + ub;   // (nbase/128)*32 + ub
    const float* prer = g_prectx + (size_t)gr * 4096 + nbase;
    const float* pbr  = g_pbdec + nbase;
    const float* smr  = sm + row * 132;
#pragma unroll 4
    for (int t = 0; t < 16; t++) {
        const int u = ub + t;
        float gi = smr[u]      + prer[u]      + pbr[u];
        float gf = smr[32 + u] + prer[32 + u] + pbr[32 + u];
        float gg = smr[64 + u] + prer[64 + u] + pbr[64 + u];
        float go = smr[96 + u] + prer[96 + u] + pbr[96 + u];
        const size_t ci = (size_t)gr * 1024 + unit0 + t;
        float c = sigm(gf) * g_dc[ci] + sigm(gi) * tanhf(gg);
        float h = sigm(go) * tanhf(c);
        g_dc[ci] = c;
        __nv_bfloat16 hi, lo; split_bf(h, hi, lo);
        hdst_hi[ci] = hi; hdst_lo[ci] = lo;
        const size_t hx = (size_t)n * (SB * LHD) + ci;
        g_histhi[hx] = hi; g_histlo[hx] = lo;
    }
}

// ============== generic merged-pass split GEMM (2-stage) ====================
__global__ void __launch_bounds__(256, 2) gemm3m_kernel(
    const __nv_bfloat16* __restrict__ Ahi, const __nv_bfloat16* __restrict__ Alo, int lda,
    const __nv_bfloat16* __restrict__ Bhi, const __nv_bfloat16* __restrict__ Blo, int ldb,
    float* __restrict__ C, int ldc, int K,
    const float* __restrict__ bias, int out_mode)
{
    extern __shared__ char smem[];
    const uint32_t sb = smem_u32(smem);
    const int tid  = threadIdx.x;
    const int lane = tid & 31;
    const int wid  = tid >> 5;
    const int mbase = blockIdx.y * 128;
    const int nbase = blockIdx.x * 128;
    const int wm = (wid & 3) * 32;
    const int wn = (wid >> 2) * 64;

    const int NK = K / 32;

    const int lrow = tid >> 2;
    const int lc   = tid & 3;
    const int t8 = lane >> 3;
    const int r8 = lane & 7;
    const uint32_t a_lane = (uint32_t)((wm + (t8 & 1) * 8 + r8) * 80 + (t8 >> 1) * 16);
    const uint32_t b_lane = (uint32_t)((wn + (t8 >> 1) * 8 + r8) * 80 + (t8 & 1) * 16);

    float acc[2][8][4];
#pragma unroll
    for (int i = 0; i < 2; i++)
#pragma unroll
        for (int j = 0; j < 8; j++)
#pragma unroll
            for (int v = 0; v < 4; v++) acc[i][j][v] = 0.0f;

    auto load_chunk = [&](int kt) {
        const int slot = kt & 1;
        const int kk = kt * 32;
        const uint32_t st = sb + slot * G2STAGE;
        int row = lrow;
#pragma unroll
        for (int it = 0; it < 2; it++, row += 64) {
            const uint32_t d = st + row * 80 + lc * 16;
            const size_t ao = (size_t)(mbase + row) * lda + kk + lc * 8;
            cp16(d,         Ahi + ao);
            cp16(d + 10240, Alo + ao);
            const size_t bo = (size_t)(nbase + row) * ldb + kk + lc * 8;
            cp16(d + 20480, Bhi + bo);
            cp16(d + 30720, Blo + bo);
        }
    };

    load_chunk(0); cp_commit();
    if (NK > 1) load_chunk(1);
    cp_commit();

    for (int kt = 0; kt < NK; kt++) {
        cp_wait1();
        __syncthreads();
        const uint32_t st = sb + (kt & 1) * G2STAGE;
#pragma unroll
        for (int ks = 0; ks < 2; ks++) {
            uint32_t ah[2][4], bh[4][4];
#pragma unroll
            for (int mi = 0; mi < 2; mi++)
                ldsm4(ah[mi], st + a_lane + mi * 16 * 80 + ks * 32);
#pragma unroll
            for (int bi = 0; bi < 4; bi++)
                ldsm4(bh[bi], st + 20480 + b_lane + bi * 16 * 80 + ks * 32);
#pragma unroll
            for (int mi = 0; mi < 2; mi++)
#pragma unroll
                for (int ni = 0; ni < 8; ni++)
                    mma16816(acc[mi][ni], ah[mi], bh[ni >> 1][(ni & 1) * 2], bh[ni >> 1][(ni & 1) * 2 + 1]);
            {
                uint32_t al[2][4];
#pragma unroll
                for (int mi = 0; mi < 2; mi++)
                    ldsm4(al[mi], st + 10240 + a_lane + mi * 16 * 80 + ks * 32);
#pragma unroll
                for (int mi = 0; mi < 2; mi++)
#pragma unroll
                    for (int ni = 0; ni < 8; ni++)
                        mma16816(acc[mi][ni], al[mi], bh[ni >> 1][(ni & 1) * 2], bh[ni >> 1][(ni & 1) * 2 + 1]);
            }
            {
                uint32_t bl[4][4];
#pragma unroll
                for (int bi = 0; bi < 4; bi++)
                    ldsm4(bl[bi], st + 30720 + b_lane + bi * 16 * 80 + ks * 32);
#pragma unroll
                for (int mi = 0; mi < 2; mi++)
#pragma unroll
                    for (int ni = 0; ni < 8; ni++)
                        mma16816(acc[mi][ni], ah[mi], bl[ni >> 1][(ni & 1) * 2], bl[ni >> 1][(ni & 1) * 2 + 1]);
            }
        }
        __syncthreads();
        if (kt + 2 < NK) load_chunk(kt + 2);
        cp_commit();
    }

    const int col0 = nbase + wn + (lane & 3) * 2;
#pragma unroll
    for (int mi = 0; mi < 2; mi++) {
        const int row0 = mbase + wm + mi * 16 + (lane >> 2);
#pragma unroll
        for (int ni = 0; ni < 8; ni++) {
            const int col = col0 + ni * 8;
            float b0 = 0.f, b1 = 0.f;
            if (bias) { b0 = bias[col]; b1 = bias[col + 1]; }
            float *p0, *p1;
            if (out_mode == 2) {
                int r0 = row0;
                int nn = r0 >> 12, ss = (r0 >> 8) & 15, bb = r0 & 255;
                p0 = C + ((size_t)bb * (SSS * NNN) + (size_t)(ss * NNN + nn)) * TT + col;
                int r1 = row0 + 8;
                nn = r1 >> 12; ss = (r1 >> 8) & 15; bb = r1 & 255;
                p1 = C + ((size_t)bb * (SSS * NNN) + (size_t)(ss * NNN + nn)) * TT + col;
            } else {
                p0 = C + (size_t)row0 * ldc + col;
                p1 = p0 + (size_t)8 * ldc;
            }
            *(float2*)p0 = make_float2(acc[mi][ni][0] + b0, acc[mi][ni][1] + b1);
            *(float2*)p1 = make_float2(acc[mi][ni][2] + b0, acc[mi][ni][3] + b1);
        }
    }
}

// ---------------- fp32 SIMT GEMM (lin only) ---------------------------------
#define BM 128
#define BN 128
#define BK 8

__global__ void __launch_bounds__(256) sgemm_kernel(
    const float* __restrict__ A, int lda,
    const float* __restrict__ B, int ldb,
    float* __restrict__ C, int ldc, int K,
    const float* __restrict__ bias, int act)
{
    __shared__ float As[2][BK][BM];
    __shared__ float Bs[2][BK][BN];

    const int tid = threadIdx.x;
    const int brow = blockIdx.y, bcol = blockIdx.x;
    const float* Ab = A + (size_t)brow * BM * lda;
    const float* Bb = B + (size_t)bcol * BN * ldb;

    const int lrow = tid >> 1;
    const int lcol = (tid & 1) * 4;
    const int tm = (tid >> 4) * 8;
    const int tn = (tid & 15) * 8;

    float acc[8][8];
#pragma unroll
    for (int i = 0; i < 8; i++)
#pragma unroll
        for (int j = 0; j < 8; j++) acc[i][j] = 0.0f;

    float4 a0 = *(const float4*)(Ab + (size_t)lrow * lda + lcol);
    float4 b0 = *(const float4*)(Bb + (size_t)lrow * ldb + lcol);
    As[0][lcol + 0][lrow] = a0.x; As[0][lcol + 1][lrow] = a0.y;
    As[0][lcol + 2][lrow] = a0.z; As[0][lcol + 3][lrow] = a0.w;
    Bs[0][lcol + 0][lrow] = b0.x; Bs[0][lcol + 1][lrow] = b0.y;
    Bs[0][lcol + 2][lrow] = b0.z; Bs[0][lcol + 3][lrow] = b0.w;
    __syncthreads();

    const int nk = K / BK;
    int buf = 0;
    for (int kt = 0; kt < nk; kt++) {
        float4 an, bn;
        const bool more = (kt + 1 < nk);
        if (more) {
            an = *(const float4*)(Ab + (size_t)lrow * lda + (kt + 1) * BK + lcol);
            bn = *(const float4*)(Bb + (size_t)lrow * ldb + (kt + 1) * BK + lcol);
        }
#pragma unroll
        for (int k = 0; k < BK; k++) {
            float af[8], bf[8];
            *(float4*)(af)     = *(const float4*)(&As[buf][k][tm]);
            *(float4*)(af + 4) = *(const float4*)(&As[buf][k][tm + 4]);
            *(float4*)(bf)     = *(const float4*)(&Bs[buf][k][tn]);
            *(float4*)(bf + 4) = *(const float4*)(&Bs[buf][k][tn + 4]);
#pragma unroll
            for (int i = 0; i < 8; i++)
#pragma unroll
                for (int j = 0; j < 8; j++)
                    acc[i][j] = fmaf(af[i], bf[j], acc[i][j]);
        }
        if (more) {
            buf ^= 1;
            As[buf][lcol + 0][lrow] = an.x; As[buf][lcol + 1][lrow] = an.y;
            As[buf][lcol + 2][lrow] = an.z; As[buf][lcol + 3][lrow] = an.w;
            Bs[buf][lcol + 0][lrow] = bn.x; Bs[buf][lcol + 1][lrow] = bn.y;
            Bs[buf][lcol + 2][lrow] = bn.z; Bs[buf][lcol + 3][lrow] = bn.w;
            __syncthreads();
        }
    }

    const int m0 = brow * BM + tm;
    const int n0 = bcol * BN + tn;
#pragma unroll
    for (int i = 0; i < 8; i++) {
        float* crow = C + (size_t)(m0 + i) * ldc;
        float v[8];
#pragma unroll
        for (int j = 0; j < 8; j++) {
            float t = acc[i][j];
            if (bias) t += bias[n0 + j];
            if (act == 1) t = tanhf(t);
            v[j] = t;
        }
        *(float4*)(crow + n0)     = make_float4(v[0], v[1], v[2], v[3]);
        *(float4*)(crow + n0 + 4) = make_float4(v[4], v[5], v[6], v[7]);
    }
}

// ---------------- elementwise / conversion kernels --------------------------
__global__ void lin_split_kernel() {
    int idx = blockIdx.x * blockDim.x + threadIdx.x;  // 256*1024
    int b = idx >> 10, u = idx & 1023;
    float h = g_decin[b * 2048 + u];
    __nv_bfloat16 hi, lo; split_bf(h, hi, lo);
    g_hhi[idx] = hi; g_hlo[idx] = lo;
    g_c[idx] = g_decin[b * 2048 + 1024 + u];
}

__global__ void cond_cell_kernel(const float* __restrict__ bih,
                                 const float* __restrict__ bhh, int s) {
    int idx = blockIdx.x * blockDim.x + threadIdx.x;  // 256*1024
    int b = idx >> 10, u = idx & 1023;
    const float* g = g_gc + (size_t)b * 4096;
    float gi = g[u]        + bih[u]        + bhh[u];
    float gf = g[1024 + u] + bih[1024 + u] + bhh[1024 + u];
    float gg = g[2048 + u] + bih[2048 + u] + bhh[2048 + u];
    float go = g[3072 + u] + bih[3072 + u] + bhh[3072 + u];
    float c = sigm(gf) * g_c[idx] + sigm(gi) * tanhf(gg);
    float h = sigm(go) * tanhf(c);
    g_c[idx] = c;
    __nv_bfloat16 hi, lo; split_bf(h, hi, lo);
    g_hhi[idx] = hi; g_hlo[idx] = lo;
    g_cohi[(size_t)s * BB * CHD + idx] = hi;
    g_colo[(size_t)s * BB * CHD + idx] = lo;
}

__global__ void split_decin_kernel() {
    int idx = blockIdx.x * blockDim.x + threadIdx.x;  // 4096*2048
    int r = idx >> 11, u = idx & 2047;
    float v = g_decin[idx];
    __nv_bfloat16 hi, lo; split_bf(v, hi, lo);
    g_dinhi[idx] = hi; g_dinlo[idx] = lo;
    if (u < 1024) {
        g_hhi[r * 1024 + u] = hi;
        g_hlo[r * 1024 + u] = lo;
    } else {
        g_dc[r * 1024 + (u - 1024)] = v;
    }
}

// ---------- one-time weight conversions ----------
__global__ void conv_w_kernel(const float* __restrict__ dec_Wih,
                              const float* __restrict__ dec_Whh) {
    int idx = blockIdx.x * blockDim.x + threadIdx.x;
    if (idx >= 4 * LHD * KW) return;
    int row = idx / KW, k = idx - row * KW;
    int orig = perm_orig(row);
    float v = (k < TT) ? dec_Wih[(size_t)orig * 2560 + 2048 + k]
                       : dec_Whh[(size_t)orig * 1024 + (k - TT)];
    __nv_bfloat16 hi, lo; split_bf(v, hi, lo);
    g_whi[idx] = hi; g_wlo[idx] = lo;
}

__global__ void conv_x_kernel(const float* __restrict__ x) {
    int idx = blockIdx.x * blockDim.x + threadIdx.x;
    float v = x[idx];
    __nv_bfloat16 hi, lo; split_bf(v, hi, lo);
    g_xhi[idx] = hi; g_xlo[idx] = lo;
}

__global__ void conv_cw_kernel(const float* __restrict__ w) {
    int idx = blockIdx.x * blockDim.x + threadIdx.x;
    __nv_bfloat16 hi, lo; split_bf(w[idx], hi, lo);
    g_cwhi[idx] = hi; g_cwlo[idx] = lo;
}

__global__ void conv_wctx_kernel(const float* __restrict__ dec_Wih) {
    int idx = blockIdx.x * blockDim.x + threadIdx.x;
    int row = idx >> 11, k = idx & 2047;
    __nv_bfloat16 hi, lo;
    split_bf(dec_Wih[(size_t)perm_orig(row) * 2560 + k], hi, lo);
    g_wctxhi[idx] = hi; g_wctxlo[idx] = lo;
}

__global__ void conv_ow_kernel(const float* __restrict__ w) {
    int idx = blockIdx.x * blockDim.x + threadIdx.x;
    __nv_bfloat16 hi, lo; split_bf(w[idx], hi, lo);
    g_owhi[idx] = hi; g_owlo[idx] = lo;
}

__global__ void conv_pw_kernel(const float* __restrict__ w) {
    int idx = blockIdx.x * blockDim.x + threadIdx.x;
    __nv_bfloat16 hi, lo; split_bf(w[idx], hi, lo);
    g_pwhi[idx] = hi; g_pwlo[idx] = lo;
}

__global__ void conv_pbdec_kernel(const float* __restrict__ dbih,
                                  const float* __restrict__ dbhh) {
    int r = blockIdx.x * blockDim.x + threadIdx.x;  // 4096
    if (r >= 4096) return;
    int orig = perm_orig(r);
    g_pbdec[r] = dbih[orig] + dbhh[orig];
}

// ---------------- launch ----------------------------------------------------
extern "C" void kernel_launch(void* const* d_in, const int* in_sizes, int n_in,
                              void* d_out, int out_size) {
    const float* z        = (const float*)d_in[0];
    const float* x        = (const float*)d_in[1];
    const float* lin_in_w = (const float*)d_in[2];
    const float* lin_in_b = (const float*)d_in[3];
    const float* cond_Whh = (const float*)d_in[5];
    const float* cond_bih = (const float*)d_in[6];
    const float* cond_bhh = (const float*)d_in[7];
    const float* pre_w    = (const float*)d_in[8];
    const float* pre_b    = (const float*)d_in[9];
    const float* dec_Wih  = (const float*)d_in[10];
    const float* dec_Whh  = (const float*)d_in[11];
    const float* dec_bih  = (const float*)d_in[12];
    const float* dec_bhh  = (const float*)d_in[13];
    const float* out_w    = (const float*)d_in[14];
    const float* out_b    = (const float*)d_in[15];
    float* out = (float*)d_out;

    float *pdecin, *pprectx, *pgc;
    __nv_bfloat16 *phhi, *phlo, *ph2hi, *ph2lo, *pcwhi, *pcwlo, *pcohi, *pcolo,
                  *pdinhi, *pdinlo, *pwctxhi, *pwctxlo, *powhi, *powlo,
                  *ppwhi, *ppwlo, *phisthi, *phistlo;
    cudaGetSymbolAddress((void**)&pdecin,  g_decin);
    cudaGetSymbolAddress((void**)&pprectx, g_prectx);
    cudaGetSymbolAddress((void**)&pgc,     g_gc);
    cudaGetSymbolAddress((void**)&phhi,    g_hhi);
    cudaGetSymbolAddress((void**)&phlo,    g_hlo);
    cudaGetSymbolAddress((void**)&ph2hi,   g_h2hi);
    cudaGetSymbolAddress((void**)&ph2lo,   g_h2lo);
    cudaGetSymbolAddress((void**)&pcwhi,   g_cwhi);
    cudaGetSymbolAddress((void**)&pcwlo,   g_cwlo);
    cudaGetSymbolAddress((void**)&pcohi,   g_cohi);
    cudaGetSymbolAddress((void**)&pcolo,   g_colo);
    cudaGetSymbolAddress((void**)&pdinhi,  g_dinhi);
    cudaGetSymbolAddress((void**)&pdinlo,  g_dinlo);
    cudaGetSymbolAddress((void**)&pwctxhi, g_wctxhi);
    cudaGetSymbolAddress((void**)&pwctxlo, g_wctxlo);
    cudaGetSymbolAddress((void**)&powhi,   g_owhi);
    cudaGetSymbolAddress((void**)&powlo,   g_owlo);
    cudaGetSymbolAddress((void**)&ppwhi,   g_pwhi);
    cudaGetSymbolAddress((void**)&ppwlo,   g_pwlo);
    cudaGetSymbolAddress((void**)&phisthi, g_histhi);
    cudaGetSymbolAddress((void**)&phistlo, g_histlo);

    cudaFuncSetAttribute(gemm3m_kernel,     cudaFuncAttributeMaxDynamicSharedMemorySize, G2SMEM);
    cudaFuncSetAttribute(gemm_gates_kernel, cudaFuncAttributeMaxDynamicSharedMemorySize, G2SMEM);

    // one-time conversions
    conv_w_kernel<<<(4 * LHD * KW + 255) / 256, 256>>>(dec_Wih, dec_Whh);
    conv_x_kernel<<<(BB * SSS * NNN * TT) / 256, 256>>>(x);
    conv_cw_kernel<<<(4 * CHD * CHD) / 256, 256>>>(cond_Whh);
    conv_wctx_kernel<<<(4 * LHD * 2 * LHD) / 256, 256>>>(dec_Wih);
    conv_ow_kernel<<<(TT * LHD) / 256, 256>>>(out_w);
    conv_pw_kernel<<<(2 * LHD * CHD) / 256, 256>>>(pre_w);
    conv_pbdec_kernel<<<16, 256>>>(dec_bih, dec_bhh);

    // hc0 = tanh(z @ lin_in_w^T + b)
    sgemm_kernel<<<dim3(2048 / BN, BB / BM), 256>>>(
        z, 512, lin_in_w, 512, pdecin, 2048, 512, lin_in_b, 1);
    lin_split_kernel<<<(BB * CHD) / 256, 256>>>();

    // cond LSTM (merged-pass GEMM, natural layout)
    for (int s = 0; s < SSS; s++) {
        gemm3m_kernel<<<dim3(32, 2), 256, G2SMEM>>>(
            phhi, phlo, 1024, pcwhi, pcwlo, 1024, pgc, 4096, 1024, nullptr, 0);
        cond_cell_kernel<<<(BB * CHD) / 256, 256>>>(cond_bih, cond_bhh, s);
    }

    // dec_in = cond_outs @ pre_w^T + pre_b
    gemm3m_kernel<<<dim3(16, 32), 256, G2SMEM>>>(
        pcohi, pcolo, 1024, ppwhi, ppwlo, 1024, pdecin, 2048, 1024, pre_b, 0);
    split_decin_kernel<<<(SB * 2 * LHD) / 256, 256>>>();

    // pre_ctx = dec_in @ W_ctx^T  (permuted cols)
    gemm3m_kernel<<<dim3(32, 32), 256, G2SMEM>>>(
        pdinhi, pdinlo, 2048, pwctxhi, pwctxlo, 2048, pprectx, 4096, 2048, nullptr, 0);

    // decoder loop: fused gates+cell, h ping-pong, history into g_hist
    for (int n = 0; n < NNN; n++) {
        const __nv_bfloat16* shi = (n & 1) ? ph2hi : phhi;
        const __nv_bfloat16* slo = (n & 1) ? ph2lo : phlo;
        __nv_bfloat16* dhi = (n & 1) ? phhi : ph2hi;
        __nv_bfloat16* dlo = (n & 1) ? phlo : ph2lo;
        gemm_gates_kernel<<<dim3(32, 32), 256, G2SMEM>>>(n, shi, slo, dhi, dlo);
    }

    // batched out-projection: hist (65536 x 1024) @ out_w^T + out_b, scatter
    gemm3m_kernel<<<dim3(4, 512), 256, G2SMEM>>>(
        phisthi, phistlo, 1024, powhi, powlo, 1024, out, TT, 1024, out_b, 2);
}

// round 17
// speedup vs baseline: 1.5021x; 1.5021x over previous
#include <cuda_runtime.h>
#include <cuda_bf16.h>
#include <cuda_fp16.h>
#include <math.h>
#include <stdint.h>

// Problem dims
#define BB 256
#define TT 512
#define CHD 1024
#define LHD 1024
#define SSS 16
#define NNN 16
#define SB 4096
#define KW 1536

// ---------------- scratch (device globals) ----------------------------------
__device__ float g_c[BB * CHD];
__device__ float g_gc[BB * 4 * CHD];
__device__ float g_decin[SB * 2 * LHD];
__device__ float g_prectx[SB * 4 * LHD];
__device__ float g_dc[SB * LHD];
__device__ float g_gates[SB * 4 * LHD];
__device__ __nv_bfloat16 g_hhi[SB * LHD], g_hlo[SB * LHD];     // bf16 h (cond)
__device__ __half g_hfhi[SB * LHD], g_hflo[SB * LHD];          // fp16 h (dec gates)
__device__ __half g_wfhi[4 * LHD * KW];                        // [Wtok|Whh] fp16 hi
__device__ __half g_xfhi[BB * SSS * NNN * TT], g_xflo[BB * SSS * NNN * TT];
__device__ __nv_bfloat16 g_cwhi[4 * CHD * CHD], g_cwlo[4 * CHD * CHD];
__device__ __nv_bfloat16 g_wctxhi[4 * LHD * 2 * LHD], g_wctxlo[4 * LHD * 2 * LHD];
__device__ __nv_bfloat16 g_owhi[TT * LHD], g_owlo[TT * LHD];
__device__ __nv_bfloat16 g_pwhi[2 * LHD * CHD], g_pwlo[2 * LHD * CHD];
__device__ __nv_bfloat16 g_cohi[SSS * BB * CHD], g_colo[SSS * BB * CHD];
__device__ __nv_bfloat16 g_dinhi[SB * 2 * LHD], g_dinlo[SB * 2 * LHD];
__device__ __nv_bfloat16 g_histhi[NNN * SB * LHD], g_histlo[NNN * SB * LHD];

__device__ __forceinline__ float sigm(float x) { return 1.0f / (1.0f + expf(-x)); }
__device__ __forceinline__ void split_bf(float v, __nv_bfloat16& hi, __nv_bfloat16& lo) {
    hi = __float2bfloat16(v);
    lo = __float2bfloat16(v - __bfloat162float(hi));
}
__device__ __forceinline__ void split_hf(float v, __half& hi, __half& lo) {
    hi = __float2half(v);
    lo = __float2half(v - __half2float(hi));
}

// ==================== PTX helpers (sm_80-portable only) =====================
__device__ __forceinline__ uint32_t smem_u32(const void* p) {
    uint32_t a;
    asm("{ .reg .u64 t; cvta.to.shared.u64 t, %1; cvt.u32.u64 %0, t; }" : "=r"(a) : "l"(p));
    return a;
}
__device__ __forceinline__ void cp16(uint32_t d, const void* s) {
    asm volatile("cp.async.cg.shared.global [%0], [%1], 16;" :: "r"(d), "l"(s));
}
__device__ __forceinline__ void cp_commit() {
    asm volatile("cp.async.commit_group;" ::: "memory");
}
__device__ __forceinline__ void cp_wait1() {
    asm volatile("cp.async.wait_group 1;" ::: "memory");
}
__device__ __forceinline__ void cp_wait2() {
    asm volatile("cp.async.wait_group 2;" ::: "memory");
}
__device__ __forceinline__ void ldsm4(uint32_t* r, uint32_t addr) {
    asm volatile("ldmatrix.sync.aligned.m8n8.x4.shared.b16 {%0,%1,%2,%3}, [%4];"
                 : "=r"(r[0]), "=r"(r[1]), "=r"(r[2]), "=r"(r[3]) : "r"(addr));
}
__device__ __forceinline__ void mma16816(float* c, const uint32_t* a, uint32_t b0, uint32_t b1) {
    asm volatile(
        "mma.sync.aligned.m16n8k16.row.col.f32.bf16.bf16.f32 "
        "{%0,%1,%2,%3}, {%4,%5,%6,%7}, {%8,%9}, {%0,%1,%2,%3};"
        : "+f"(c[0]), "+f"(c[1]), "+f"(c[2]), "+f"(c[3])
        : "r"(a[0]), "r"(a[1]), "r"(a[2]), "r"(a[3]), "r"(b0), "r"(b1));
}
__device__ __forceinline__ void hmma16816(float* c, const uint32_t* a, uint32_t b0, uint32_t b1) {
    asm volatile(
        "mma.sync.aligned.m16n8k16.row.col.f32.f16.f16.f32 "
        "{%0,%1,%2,%3}, {%4,%5,%6,%7}, {%8,%9}, {%0,%1,%2,%3};"
        : "+f"(c[0]), "+f"(c[1]), "+f"(c[2]), "+f"(c[3])
        : "r"(a[0]), "r"(a[1]), "r"(a[2]), "r"(a[3]), "r"(b0), "r"(b1));
}

// merged-pass 2-stage (gemm3m): Ahi|Alo|Bhi|Blo @ 80B stride, BK=32
#define G2STAGE 40960
#define G2SMEM (2 * G2STAGE)   // 81920 -> 2 CTAs/SM

// gates: fp16 2-pass, 4 stages of Ahi|Alo|Bhi, 64B rows + XOR swizzle
#define GFOP 8192              // 128 rows * 64 B per operand
#define GFSTAGE (3 * GFOP)     // 24576
#define GFSMEM (4 * GFSTAGE)   // 98304 -> 2 CTAs/SM

// swizzled 16B-chunk offset within an operand tile
__device__ __forceinline__ uint32_t swz(int r, int c) {
    return (uint32_t)(r * 64 + ((c ^ ((r >> 1) & 3)) << 4));
}

// ===== gates GEMM (dec loop): fp16 2-pass, 4-stage single-sync pipeline =====
__global__ void __launch_bounds__(256, 2) gemm_gates_kernel(int n, float* __restrict__ C)
{
    extern __shared__ char smem[];
    const uint32_t sb = smem_u32(smem);
    const int tid  = threadIdx.x;
    const int lane = tid & 31;
    const int wid  = tid >> 5;
    const int mbase = blockIdx.y * 128;
    const int nbase = blockIdx.x * 128;
    const int wm = (wid & 3) * 32;
    const int wn = (wid >> 2) * 64;

    const int K    = (n == 0) ? 1024 : KW;
    const int NK   = K / 32;
    const int wofs = (n == 0) ? 512 : 0;

    // loader: r = tid>>1, handles chunks c2, c2+1 per operand
    const int lr = tid >> 1;
    const int c2 = (tid & 1) * 2;

    const int t8 = lane >> 3;
    const int r8 = lane & 7;
    // per-lane ldsm row/base info
    const int raw_a0 = wm + (t8 & 1) * 8 + r8;       // + mi*16
    const int c0a = t8 >> 1;
    const int raw_b0 = wn + (t8 >> 1) * 8 + r8;      // + bi*16
    const int c0b = t8 & 1;

    float acc[2][8][4];
#pragma unroll
    for (int i = 0; i < 2; i++)
#pragma unroll
        for (int j = 0; j < 8; j++)
#pragma unroll
            for (int v = 0; v < 4; v++) acc[i][j][v] = 0.0f;

    auto load_chunk = [&](int kt) {
        const uint32_t st = sb + (kt & 3) * GFSTAGE;
        const int kk = kt * 32;
#pragma unroll
        for (int cc = 0; cc < 2; cc++) {
            const int c = c2 + cc;
            const uint32_t d = st + swz(lr, c);
            if (n > 0 && kk < 512) {
                const int b = (mbase + lr) & 255, s = (mbase + lr) >> 8;
                const size_t ao = ((size_t)(b * (SSS * NNN) + s * NNN + n - 1)) * TT + kk + c * 8;
                cp16(d,       g_xfhi + ao);
                cp16(d + GFOP, g_xflo + ao);
            } else {
                const int hc = (n == 0) ? kk : (kk - 512);
                const size_t ao = (size_t)(mbase + lr) * LHD + hc + c * 8;
                cp16(d,       g_hfhi + ao);
                cp16(d + GFOP, g_hflo + ao);
            }
            const size_t bo = (size_t)(nbase + lr) * KW + wofs + kk + c * 8;
            cp16(d + 2 * GFOP, g_wfhi + bo);
        }
    };

    load_chunk(0); cp_commit();
    load_chunk(1); cp_commit();
    load_chunk(2); cp_commit();

    for (int kt = 0; kt < NK; kt++) {
        cp_wait2();              // chunk kt resident (kt+1, kt+2 in flight)
        __syncthreads();         // visible to all; all warps past compute kt-1
        if (kt + 3 < NK) load_chunk(kt + 3);   // slot (kt-1)&3: free
        cp_commit();
        const uint32_t st = sb + (kt & 3) * GFSTAGE;
#pragma unroll
        for (int ks = 0; ks < 2; ks++) {
            uint32_t ah[2][4], al[2][4], bh[4][4];
#pragma unroll
            for (int mi = 0; mi < 2; mi++) {
                const int r = raw_a0 + mi * 16;
                const uint32_t off = swz(r, 2 * ks + c0a);
                ldsm4(ah[mi], st + off);
                ldsm4(al[mi], st + GFOP + off);
            }
#pragma unroll
            for (int bi = 0; bi < 4; bi++) {
                const int r = raw_b0 + bi * 16;
                ldsm4(bh[bi], st + 2 * GFOP + swz(r, 2 * ks + c0b));
            }
#pragma unroll
            for (int mi = 0; mi < 2; mi++)
#pragma unroll
                for (int ni = 0; ni < 8; ni++)
                    hmma16816(acc[mi][ni], ah[mi], bh[ni >> 1][(ni & 1) * 2], bh[ni >> 1][(ni & 1) * 2 + 1]);
#pragma unroll
            for (int mi = 0; mi < 2; mi++)
#pragma unroll
                for (int ni = 0; ni < 8; ni++)
                    hmma16816(acc[mi][ni], al[mi], bh[ni >> 1][(ni & 1) * 2], bh[ni >> 1][(ni & 1) * 2 + 1]);
        }
    }

    const int col0 = nbase + wn + (lane & 3) * 2;
#pragma unroll
    for (int mi = 0; mi < 2; mi++) {
        const int row0 = mbase + wm + mi * 16 + (lane >> 2);
#pragma unroll
        for (int ni = 0; ni < 8; ni++) {
            float* p0 = C + (size_t)row0 * 4096 + col0 + ni * 8;
            float* p1 = p0 + 8 * 4096;
            *(float2*)p0 = make_float2(acc[mi][ni][0], acc[mi][ni][1]);
            *(float2*)p1 = make_float2(acc[mi][ni][2], acc[mi][ni][3]);
        }
    }
}

// ============== generic merged-pass split GEMM (2-stage, bf16 3-pass) =======
__global__ void __launch_bounds__(256, 2) gemm3m_kernel(
    const __nv_bfloat16* __restrict__ Ahi, const __nv_bfloat16* __restrict__ Alo, int lda,
    const __nv_bfloat16* __restrict__ Bhi, const __nv_bfloat16* __restrict__ Blo, int ldb,
    float* __restrict__ C, int ldc, int K,
    const float* __restrict__ bias, int out_mode)
{
    extern __shared__ char smem[];
    const uint32_t sb = smem_u32(smem);
    const int tid  = threadIdx.x;
    const int lane = tid & 31;
    const int wid  = tid >> 5;
    const int mbase = blockIdx.y * 128;
    const int nbase = blockIdx.x * 128;
    const int wm = (wid & 3) * 32;
    const int wn = (wid >> 2) * 64;

    const int NK = K / 32;

    const int lrow = tid >> 2;
    const int lc   = tid & 3;
    const int t8 = lane >> 3;
    const int r8 = lane & 7;
    const uint32_t a_lane = (uint32_t)((wm + (t8 & 1) * 8 + r8) * 80 + (t8 >> 1) * 16);
    const uint32_t b_lane = (uint32_t)((wn + (t8 >> 1) * 8 + r8) * 80 + (t8 & 1) * 16);

    float acc[2][8][4];
#pragma unroll
    for (int i = 0; i < 2; i++)
#pragma unroll
        for (int j = 0; j < 8; j++)
#pragma unroll
            for (int v = 0; v < 4; v++) acc[i][j][v] = 0.0f;

    auto load_chunk = [&](int kt) {
        const int slot = kt & 1;
        const int kk = kt * 32;
        const uint32_t st = sb + slot * G2STAGE;
        int row = lrow;
#pragma unroll
        for (int it = 0; it < 2; it++, row += 64) {
            const uint32_t d = st + row * 80 + lc * 16;
            const size_t ao = (size_t)(mbase + row) * lda + kk + lc * 8;
            cp16(d,         Ahi + ao);
            cp16(d + 10240, Alo + ao);
            const size_t bo = (size_t)(nbase + row) * ldb + kk + lc * 8;
            cp16(d + 20480, Bhi + bo);
            cp16(d + 30720, Blo + bo);
        }
    };

    load_chunk(0); cp_commit();
    if (NK > 1) load_chunk(1);
    cp_commit();

    for (int kt = 0; kt < NK; kt++) {
        cp_wait1();
        __syncthreads();
        const uint32_t st = sb + (kt & 1) * G2STAGE;
#pragma unroll
        for (int ks = 0; ks < 2; ks++) {
            uint32_t ah[2][4], bh[4][4];
#pragma unroll
            for (int mi = 0; mi < 2; mi++)
                ldsm4(ah[mi], st + a_lane + mi * 16 * 80 + ks * 32);
#pragma unroll
            for (int bi = 0; bi < 4; bi++)
                ldsm4(bh[bi], st + 20480 + b_lane + bi * 16 * 80 + ks * 32);
#pragma unroll
            for (int mi = 0; mi < 2; mi++)
#pragma unroll
                for (int ni = 0; ni < 8; ni++)
                    mma16816(acc[mi][ni], ah[mi], bh[ni >> 1][(ni & 1) * 2], bh[ni >> 1][(ni & 1) * 2 + 1]);
            {
                uint32_t al[2][4];
#pragma unroll
                for (int mi = 0; mi < 2; mi++)
                    ldsm4(al[mi], st + 10240 + a_lane + mi * 16 * 80 + ks * 32);
#pragma unroll
                for (int mi = 0; mi < 2; mi++)
#pragma unroll
                    for (int ni = 0; ni < 8; ni++)
                        mma16816(acc[mi][ni], al[mi], bh[ni >> 1][(ni & 1) * 2], bh[ni >> 1][(ni & 1) * 2 + 1]);
            }
            {
                uint32_t bl[4][4];
#pragma unroll
                for (int bi = 0; bi < 4; bi++)
                    ldsm4(bl[bi], st + 30720 + b_lane + bi * 16 * 80 + ks * 32);
#pragma unroll
                for (int mi = 0; mi < 2; mi++)
#pragma unroll
                    for (int ni = 0; ni < 8; ni++)
                        mma16816(acc[mi][ni], ah[mi], bl[ni >> 1][(ni & 1) * 2], bl[ni >> 1][(ni & 1) * 2 + 1]);
            }
        }
        __syncthreads();
        if (kt + 2 < NK) load_chunk(kt + 2);
        cp_commit();
    }

    const int col0 = nbase + wn + (lane & 3) * 2;
#pragma unroll
    for (int mi = 0; mi < 2; mi++) {
        const int row0 = mbase + wm + mi * 16 + (lane >> 2);
#pragma unroll
        for (int ni = 0; ni < 8; ni++) {
            const int col = col0 + ni * 8;
            float b0 = 0.f, b1 = 0.f;
            if (bias) { b0 = bias[col]; b1 = bias[col + 1]; }
            float *p0, *p1;
            if (out_mode == 2) {
                int r0 = row0;
                int nn = r0 >> 12, ss = (r0 >> 8) & 15, bb = r0 & 255;
                p0 = C + ((size_t)bb * (SSS * NNN) + (size_t)(ss * NNN + nn)) * TT + col;
                int r1 = row0 + 8;
                nn = r1 >> 12; ss = (r1 >> 8) & 15; bb = r1 & 255;
                p1 = C + ((size_t)bb * (SSS * NNN) + (size_t)(ss * NNN + nn)) * TT + col;
            } else {
                p0 = C + (size_t)row0 * ldc + col;
                p1 = p0 + (size_t)8 * ldc;
            }
            *(float2*)p0 = make_float2(acc[mi][ni][0] + b0, acc[mi][ni][1] + b1);
            *(float2*)p1 = make_float2(acc[mi][ni][2] + b0, acc[mi][ni][3] + b1);
        }
    }
}

// ---------------- fp32 SIMT GEMM (lin only) ---------------------------------
#define BM 128
#define BN 128
#define BK 8

__global__ void __launch_bounds__(256) sgemm_kernel(
    const float* __restrict__ A, int lda,
    const float* __restrict__ B, int ldb,
    float* __restrict__ C, int ldc, int K,
    const float* __restrict__ bias, int act)
{
    __shared__ float As[2][BK][BM];
    __shared__ float Bs[2][BK][BN];

    const int tid = threadIdx.x;
    const int brow = blockIdx.y, bcol = blockIdx.x;
    const float* Ab = A + (size_t)brow * BM * lda;
    const float* Bb = B + (size_t)bcol * BN * ldb;

    const int lrow = tid >> 1;
    const int lcol = (tid & 1) * 4;
    const int tm = (tid >> 4) * 8;
    const int tn = (tid & 15) * 8;

    float acc[8][8];
#pragma unroll
    for (int i = 0; i < 8; i++)
#pragma unroll
        for (int j = 0; j < 8; j++) acc[i][j] = 0.0f;

    float4 a0 = *(const float4*)(Ab + (size_t)lrow * lda + lcol);
    float4 b0 = *(const float4*)(Bb + (size_t)lrow * ldb + lcol);
    As[0][lcol + 0][lrow] = a0.x; As[0][lcol + 1][lrow] = a0.y;
    As[0][lcol + 2][lrow] = a0.z; As[0][lcol + 3][lrow] = a0.w;
    Bs[0][lcol + 0][lrow] = b0.x; Bs[0][lcol + 1][lrow] = b0.y;
    Bs[0][lcol + 2][lrow] = b0.z; Bs[0][lcol + 3][lrow] = b0.w;
    __syncthreads();

    const int nk = K / BK;
    int buf = 0;
    for (int kt = 0; kt < nk; kt++) {
        float4 an, bn;
        const bool more = (kt + 1 < nk);
        if (more) {
            an = *(const float4*)(Ab + (size_t)lrow * lda + (kt + 1) * BK + lcol);
            bn = *(const float4*)(Bb + (size_t)lrow * ldb + (kt + 1) * BK + lcol);
        }
#pragma unroll
        for (int k = 0; k < BK; k++) {
            float af[8], bf[8];
            *(float4*)(af)     = *(const float4*)(&As[buf][k][tm]);
            *(float4*)(af + 4) = *(const float4*)(&As[buf][k][tm + 4]);
            *(float4*)(bf)     = *(const float4*)(&Bs[buf][k][tn]);
            *(float4*)(bf + 4) = *(const float4*)(&Bs[buf][k][tn + 4]);
#pragma unroll
            for (int i = 0; i < 8; i++)
#pragma unroll
                for (int j = 0; j < 8; j++)
                    acc[i][j] = fmaf(af[i], bf[j], acc[i][j]);
        }
        if (more) {
            buf ^= 1;
            As[buf][lcol + 0][lrow] = an.x; As[buf][lcol + 1][lrow] = an.y;
            As[buf][lcol + 2][lrow] = an.z; As[buf][lcol + 3][lrow] = an.w;
            Bs[buf][lcol + 0][lrow] = bn.x; Bs[buf][lcol + 1][lrow] = bn.y;
            Bs[buf][lcol + 2][lrow] = bn.z; Bs[buf][lcol + 3][lrow] = bn.w;
            __syncthreads();
        }
    }

    const int m0 = brow * BM + tm;
    const int n0 = bcol * BN + tn;
#pragma unroll
    for (int i = 0; i < 8; i++) {
        float* crow = C + (size_t)(m0 + i) * ldc;
        float v[8];
#pragma unroll
        for (int j = 0; j < 8; j++) {
            float t = acc[i][j];
            if (bias) t += bias[n0 + j];
            if (act == 1) t = tanhf(t);
            v[j] = t;
        }
        *(float4*)(crow + n0)     = make_float4(v[0], v[1], v[2], v[3]);
        *(float4*)(crow + n0 + 4) = make_float4(v[4], v[5], v[6], v[7]);
    }
}

// ---------------- elementwise / conversion kernels --------------------------
__global__ void lin_split_kernel() {
    int idx = blockIdx.x * blockDim.x + threadIdx.x;  // 256*1024
    int b = idx >> 10, u = idx & 1023;
    float h = g_decin[b * 2048 + u];
    __nv_bfloat16 hi, lo; split_bf(h, hi, lo);
    g_hhi[idx] = hi; g_hlo[idx] = lo;
    g_c[idx] = g_decin[b * 2048 + 1024 + u];
}

__global__ void cond_cell_kernel(const float* __restrict__ bih,
                                 const float* __restrict__ bhh, int s) {
    int idx = blockIdx.x * blockDim.x + threadIdx.x;  // 256*1024
    int b = idx >> 10, u = idx & 1023;
    const float* g = g_gc + (size_t)b * 4096;
    float gi = g[u]        + bih[u]        + bhh[u];
    float gf = g[1024 + u] + bih[1024 + u] + bhh[1024 + u];
    float gg = g[2048 + u] + bih[2048 + u] + bhh[2048 + u];
    float go = g[3072 + u] + bih[3072 + u] + bhh[3072 + u];
    float c = sigm(gf) * g_c[idx] + sigm(gi) * tanhf(gg);
    float h = sigm(go) * tanhf(c);
    g_c[idx] = c;
    __nv_bfloat16 hi, lo; split_bf(h, hi, lo);
    g_hhi[idx] = hi; g_hlo[idx] = lo;
    g_cohi[(size_t)s * BB * CHD + idx] = hi;
    g_colo[(size_t)s * BB * CHD + idx] = lo;
}

__global__ void split_decin_kernel() {
    int idx = blockIdx.x * blockDim.x + threadIdx.x;  // 4096*2048
    int r = idx >> 11, u = idx & 2047;
    float v = g_decin[idx];
    __nv_bfloat16 hi, lo; split_bf(v, hi, lo);
    g_dinhi[idx] = hi; g_dinlo[idx] = lo;
    if (u < 1024) {
        __half fhi, flo; split_hf(v, fhi, flo);
        g_hfhi[r * 1024 + u] = fhi;
        g_hflo[r * 1024 + u] = flo;
    } else {
        g_dc[r * 1024 + (u - 1024)] = v;
    }
}

__global__ void dec_cell_kernel(const float* __restrict__ bih,
                                const float* __restrict__ bhh, int n) {
    int idx = blockIdx.x * blockDim.x + threadIdx.x;  // 4096*1024
    int r = idx >> 10, u = idx & 1023;
    const float* g = g_gates  + (size_t)r * 4096;
    const float* p = g_prectx + (size_t)r * 4096;
    float gi = g[u]        + p[u]        + bih[u]        + bhh[u];
    float gf = g[1024 + u] + p[1024 + u] + bih[1024 + u] + bhh[1024 + u];
    float gg = g[2048 + u] + p[2048 + u] + bih[2048 + u] + bhh[2048 + u];
    float go = g[3072 + u] + p[3072 + u] + bih[3072 + u] + bhh[3072 + u];
    float c = sigm(gf) * g_dc[idx] + sigm(gi) * tanhf(gg);
    float h = sigm(go) * tanhf(c);
    g_dc[idx] = c;
    __half fhi, flo; split_hf(h, fhi, flo);
    g_hfhi[idx] = fhi; g_hflo[idx] = flo;
    __nv_bfloat16 hi, lo; split_bf(h, hi, lo);
    const size_t hx = (size_t)n * (SB * LHD) + idx;
    g_histhi[hx] = hi; g_histlo[hx] = lo;
}

// ---------- one-time weight conversions ----------
__global__ void conv_w_kernel(const float* __restrict__ dec_Wih,
                              const float* __restrict__ dec_Whh) {
    int idx = blockIdx.x * blockDim.x + threadIdx.x;
    if (idx >= 4 * LHD * KW) return;
    int row = idx / KW, k = idx - row * KW;
    float v = (k < TT) ? dec_Wih[(size_t)row * 2560 + 2048 + k]
                       : dec_Whh[(size_t)row * 1024 + (k - TT)];
    g_wfhi[idx] = __float2half(v);
}

__global__ void conv_x_kernel(const float* __restrict__ x) {
    int idx = blockIdx.x * blockDim.x + threadIdx.x;
    float v = x[idx];
    __half hi, lo; split_hf(v, hi, lo);
    g_xfhi[idx] = hi; g_xflo[idx] = lo;
}

__global__ void conv_cw_kernel(const float* __restrict__ w) {
    int idx = blockIdx.x * blockDim.x + threadIdx.x;
    __nv_bfloat16 hi, lo; split_bf(w[idx], hi, lo);
    g_cwhi[idx] = hi; g_cwlo[idx] = lo;
}

__global__ void conv_wctx_kernel(const float* __restrict__ dec_Wih) {
    int idx = blockIdx.x * blockDim.x + threadIdx.x;
    int row = idx >> 11, k = idx & 2047;
    __nv_bfloat16 hi, lo; split_bf(dec_Wih[(size_t)row * 2560 + k], hi, lo);
    g_wctxhi[idx] = hi; g_wctxlo[idx] = lo;
}

__global__ void conv_ow_kernel(const float* __restrict__ w) {
    int idx = blockIdx.x * blockDim.x + threadIdx.x;
    __nv_bfloat16 hi, lo; split_bf(w[idx], hi, lo);
    g_owhi[idx] = hi; g_owlo[idx] = lo;
}

__global__ void conv_pw_kernel(const float* __restrict__ w) {
    int idx = blockIdx.x * blockDim.x + threadIdx.x;
    __nv_bfloat16 hi, lo; split_bf(w[idx], hi, lo);
    g_pwhi[idx] = hi; g_pwlo[idx] = lo;
}

// ---------------- launch ----------------------------------------------------
extern "C" void kernel_launch(void* const* d_in, const int* in_sizes, int n_in,
                              void* d_out, int out_size) {
    const float* z        = (const float*)d_in[0];
    const float* x        = (const float*)d_in[1];
    const float* lin_in_w = (const float*)d_in[2];
    const float* lin_in_b = (const float*)d_in[3];
    const float* cond_Whh = (const float*)d_in[5];
    const float* cond_bih = (const float*)d_in[6];
    const float* cond_bhh = (const float*)d_in[7];
    const float* pre_w    = (const float*)d_in[8];
    const float* pre_b    = (const float*)d_in[9];
    const float* dec_Wih  = (const float*)d_in[10];
    const float* dec_Whh  = (const float*)d_in[11];
    const float* dec_bih  = (const float*)d_in[12];
    const float* dec_bhh  = (const float*)d_in[13];
    const float* out_w    = (const float*)d_in[14];
    const float* out_b    = (const float*)d_in[15];
    float* out = (float*)d_out;

    float *pdecin, *pprectx, *pgc, *pgates;
    __nv_bfloat16 *phhi, *phlo, *pcwhi, *pcwlo, *pcohi, *pcolo, *pdinhi, *pdinlo,
                  *pwctxhi, *pwctxlo, *powhi, *powlo, *ppwhi, *ppwlo, *phisthi, *phistlo;
    cudaGetSymbolAddress((void**)&pdecin,  g_decin);
    cudaGetSymbolAddress((void**)&pprectx, g_prectx);
    cudaGetSymbolAddress((void**)&pgc,     g_gc);
    cudaGetSymbolAddress((void**)&pgates,  g_gates);
    cudaGetSymbolAddress((void**)&phhi,    g_hhi);
    cudaGetSymbolAddress((void**)&phlo,    g_hlo);
    cudaGetSymbolAddress((void**)&pcwhi,   g_cwhi);
    cudaGetSymbolAddress((void**)&pcwlo,   g_cwlo);
    cudaGetSymbolAddress((void**)&pcohi,   g_cohi);
    cudaGetSymbolAddress((void**)&pcolo,   g_colo);
    cudaGetSymbolAddress((void**)&pdinhi,  g_dinhi);
    cudaGetSymbolAddress((void**)&pdinlo,  g_dinlo);
    cudaGetSymbolAddress((void**)&pwctxhi, g_wctxhi);
    cudaGetSymbolAddress((void**)&pwctxlo, g_wctxlo);
    cudaGetSymbolAddress((void**)&powhi,   g_owhi);
    cudaGetSymbolAddress((void**)&powlo,   g_owlo);
    cudaGetSymbolAddress((void**)&ppwhi,   g_pwhi);
    cudaGetSymbolAddress((void**)&ppwlo,   g_pwlo);
    cudaGetSymbolAddress((void**)&phisthi, g_histhi);
    cudaGetSymbolAddress((void**)&phistlo, g_histlo);

    cudaFuncSetAttribute(gemm3m_kernel,     cudaFuncAttributeMaxDynamicSharedMemorySize, G2SMEM);
    cudaFuncSetAttribute(gemm_gates_kernel, cudaFuncAttributeMaxDynamicSharedMemorySize, GFSMEM);

    // one-time conversions
    conv_w_kernel<<<(4 * LHD * KW + 255) / 256, 256>>>(dec_Wih, dec_Whh);
    conv_x_kernel<<<(BB * SSS * NNN * TT) / 256, 256>>>(x);
    conv_cw_kernel<<<(4 * CHD * CHD) / 256, 256>>>(cond_Whh);
    conv_wctx_kernel<<<(4 * LHD * 2 * LHD) / 256, 256>>>(dec_Wih);
    conv_ow_kernel<<<(TT * LHD) / 256, 256>>>(out_w);
    conv_pw_kernel<<<(2 * LHD * CHD) / 256, 256>>>(pre_w);

    // hc0 = tanh(z @ lin_in_w^T + b)
    sgemm_kernel<<<dim3(2048 / BN, BB / BM), 256>>>(
        z, 512, lin_in_w, 512, pdecin, 2048, 512, lin_in_b, 1);
    lin_split_kernel<<<(BB * CHD) / 256, 256>>>();

    // cond LSTM (merged-pass bf16 GEMM)
    for (int s = 0; s < SSS; s++) {
        gemm3m_kernel<<<dim3(32, 2), 256, G2SMEM>>>(
            phhi, phlo, 1024, pcwhi, pcwlo, 1024, pgc, 4096, 1024, nullptr, 0);
        cond_cell_kernel<<<(BB * CHD) / 256, 256>>>(cond_bih, cond_bhh, s);
    }

    // dec_in = cond_outs @ pre_w^T + pre_b
    gemm3m_kernel<<<dim3(16, 32), 256, G2SMEM>>>(
        pcohi, pcolo, 1024, ppwhi, ppwlo, 1024, pdecin, 2048, 1024, pre_b, 0);
    split_decin_kernel<<<(SB * 2 * LHD) / 256, 256>>>();

    // pre_ctx = dec_in @ W_ctx^T
    gemm3m_kernel<<<dim3(32, 32), 256, G2SMEM>>>(
        pdinhi, pdinlo, 2048, pwctxhi, pwctxlo, 2048, pprectx, 4096, 2048, nullptr, 0);

    // decoder loop (fp16 2-pass gates GEMM + cell; cell appends history)
    for (int n = 0; n < NNN; n++) {
        gemm_gates_kernel<<<dim3(32, 32), 256, GFSMEM>>>(n, pgates);
        dec_cell_kernel<<<(SB * LHD) / 256, 256>>>(dec_bih, dec_bhh, n);
    }

    // batched out-projection: hist (65536 x 1024) @ out_w^T + out_b, scatter
    gemm3m_kernel<<<dim3(4, 512), 256, G2SMEM>>>(
        phisthi, phistlo, 1024, powhi, powlo, 1024, out, TT, 1024, out_b, 2);
}